// round 2
// baseline (speedup 1.0000x reference)
#include <cuda_runtime.h>

#define B 4096
#define D 128
#define TEMP 100.0f

#define BM 128
#define BN 128
#define BK 32
#define TM 8
#define TN 8
#define NTHREADS 256
#define SLICES 16
#define COLS_PER_SLICE (B / SLICES)   // 256
#define JT (COLS_PER_SLICE / BN)      // 2
#define ROWB (B / BM)                 // 32

// Scratch (no allocations allowed in kernel_launch)
__device__ float g_sq[B];
__device__ int   g_lab[B];
__device__ float g_pden[SLICES][B];
__device__ float g_pnum[SLICES][B];

// ---------------------------------------------------------------------------
// Kernel 1: per-row squared norms + label copy (y arrives as int32)
// ---------------------------------------------------------------------------
__global__ void snn_prep(const float* __restrict__ x,
                         const int* __restrict__ y) {
    int i = blockIdx.x * blockDim.x + threadIdx.x;
    if (i < B) {
        const float4* xr = reinterpret_cast<const float4*>(x + (size_t)i * D);
        float s = 0.f;
        #pragma unroll
        for (int k = 0; k < D / 4; k++) {
            float4 v = xr[k];
            s += v.x * v.x + v.y * v.y + v.z * v.z + v.w * v.w;
        }
        g_sq[i]  = s;
        g_lab[i] = y[i];
    }
}

// ---------------------------------------------------------------------------
// Kernel 2: fused Gram-tile GEMM + exp + masked row reductions.
// Block (bx, by): rows [bx*128, bx*128+128), cols slice by: [by*256, by*256+256)
// 256 threads, each owns an 8x8 micro-tile. Smem tiles stored k-major so the
// inner loop does conflict-free LDS.128 fragment loads.
// ---------------------------------------------------------------------------
__global__ void __launch_bounds__(NTHREADS)
snn_main(const float* __restrict__ x) {
    __shared__ float As[BK][BM + 4];   // [k][row], +4 pad keeps 16B alignment
    __shared__ float Bs[BK][BN + 4];   // [k][col]
    __shared__ float s_sqj[BN];
    __shared__ int   s_labj[BN];

    const int tid = threadIdx.x;
    const int tx  = tid & 15;
    const int ty  = tid >> 4;
    const int row0  = blockIdx.x * BM;
    const int slice = blockIdx.y;
    const int colsl = slice * COLS_PER_SLICE;

    float sqi[TM];
    int   labi[TM];
    #pragma unroll
    for (int r = 0; r < TM; r++) {
        int gi  = row0 + ty * TM + r;
        sqi[r]  = g_sq[gi];
        labi[r] = g_lab[gi];
    }

    float dsum[TM], nsum[TM];
    #pragma unroll
    for (int r = 0; r < TM; r++) { dsum[r] = 0.f; nsum[r] = 0.f; }

    const float NEGC = -1.4426950408889634f / TEMP;  // -log2(e)/T

    for (int jt = 0; jt < JT; jt++) {
        const int col0 = colsl + jt * BN;

        __syncthreads();  // previous epilogue done before rewriting s_sqj
        if (tid < BN) {
            s_sqj[tid]  = g_sq[col0 + tid];
            s_labj[tid] = g_lab[col0 + tid];
        }

        float acc[TM][TN];
        #pragma unroll
        for (int r = 0; r < TM; r++)
            #pragma unroll
            for (int c = 0; c < TN; c++)
                acc[r][c] = 0.f;

        for (int kc = 0; kc < D; kc += BK) {
            __syncthreads();  // previous k-chunk compute done before overwrite
            // Load A and B tiles (128 rows x 32 k each), transposed to k-major.
            #pragma unroll
            for (int l = 0; l < 4; l++) {
                int idx = tid + l * NTHREADS;  // 0..1023
                int r   = idx >> 3;            // 0..127
                int kq  = idx & 7;             // 0..7 (float4 chunk along k)
                float4 va = *reinterpret_cast<const float4*>(
                    x + (size_t)(row0 + r) * D + kc + kq * 4);
                As[kq * 4 + 0][r] = va.x;
                As[kq * 4 + 1][r] = va.y;
                As[kq * 4 + 2][r] = va.z;
                As[kq * 4 + 3][r] = va.w;
                float4 vb = *reinterpret_cast<const float4*>(
                    x + (size_t)(col0 + r) * D + kc + kq * 4);
                Bs[kq * 4 + 0][r] = vb.x;
                Bs[kq * 4 + 1][r] = vb.y;
                Bs[kq * 4 + 2][r] = vb.z;
                Bs[kq * 4 + 3][r] = vb.w;
            }
            __syncthreads();

            #pragma unroll
            for (int k = 0; k < BK; k++) {
                float a[TM], b[TN];
                *reinterpret_cast<float4*>(a)     = *reinterpret_cast<const float4*>(&As[k][ty * TM]);
                *reinterpret_cast<float4*>(a + 4) = *reinterpret_cast<const float4*>(&As[k][ty * TM + 4]);
                *reinterpret_cast<float4*>(b)     = *reinterpret_cast<const float4*>(&Bs[k][tx * TN]);
                *reinterpret_cast<float4*>(b + 4) = *reinterpret_cast<const float4*>(&Bs[k][tx * TN + 4]);
                #pragma unroll
                for (int r = 0; r < TM; r++)
                    #pragma unroll
                    for (int c = 0; c < TN; c++)
                        acc[r][c] = fmaf(a[r], b[c], acc[r][c]);
            }
        }

        // Epilogue: dist -> exp -> masked accumulation (no gmem traffic)
        #pragma unroll
        for (int r = 0; r < TM; r++) {
            int gi = row0 + ty * TM + r;
            #pragma unroll
            for (int c = 0; c < TN; c++) {
                int   gj   = col0 + tx * TN + c;
                float dist = sqi[r] + s_sqj[tx * TN + c] - 2.f * acc[r][c];
                dist = fmaxf(dist, 0.f);
                float e = exp2f(dist * NEGC);
                bool self = (gi == gj);
                if (self) e = 1.f;  // reference: diag dist clamps to ~0 -> e=1
                dsum[r] += e;
                bool samecls = (labi[r] == s_labj[tx * TN + c]) && !self;
                nsum[r] += samecls ? e : 0.f;
            }
        }
    }

    // Cross-thread (tx) reduction of the per-row partial sums; reuse As smem.
    float* red = &As[0][0];  // 128*16 floats = 2048 <= 32*132
    __syncthreads();
    #pragma unroll
    for (int r = 0; r < TM; r++) red[(ty * TM + r) * 16 + tx] = dsum[r];
    __syncthreads();
    if (tid < BM) {
        float s = 0.f;
        #pragma unroll
        for (int t = 0; t < 16; t++) s += red[tid * 16 + t];
        g_pden[slice][row0 + tid] = s;
    }
    __syncthreads();
    #pragma unroll
    for (int r = 0; r < TM; r++) red[(ty * TM + r) * 16 + tx] = nsum[r];
    __syncthreads();
    if (tid < BM) {
        float s = 0.f;
        #pragma unroll
        for (int t = 0; t < 16; t++) s += red[tid * 16 + t];
        g_pnum[slice][row0 + tid] = s;
    }
}

// ---------------------------------------------------------------------------
// Kernel 3: combine slice partials, mean(-log(num/den))
// ---------------------------------------------------------------------------
__global__ void snn_finalize(float* __restrict__ out) {
    __shared__ float sred[NTHREADS];
    int tid = threadIdx.x;
    float s = 0.f;
    for (int i = tid; i < B; i += NTHREADS) {
        float den = 0.f, num = 0.f;
        #pragma unroll
        for (int p = 0; p < SLICES; p++) {
            den += g_pden[p][i];
            num += g_pnum[p][i];
        }
        s += logf(den) - logf(num);  // == -log(num/den)
    }
    sred[tid] = s;
    __syncthreads();
    for (int off = NTHREADS / 2; off > 0; off >>= 1) {
        if (tid < off) sred[tid] += sred[tid + off];
        __syncthreads();
    }
    if (tid == 0) out[0] = sred[0] / (float)B;
}

// ---------------------------------------------------------------------------
extern "C" void kernel_launch(void* const* d_in, const int* in_sizes, int n_in,
                              void* d_out, int out_size) {
    const float* x = (const float*)d_in[0];
    const int*   y = (const int*)d_in[1];
    float* out = (float*)d_out;

    snn_prep<<<(B + 255) / 256, 256>>>(x, y);
    dim3 grid(ROWB, SLICES);
    snn_main<<<grid, NTHREADS>>>(x);
    snn_finalize<<<1, NTHREADS>>>(out);
}

// round 4
// speedup vs baseline: 2.5295x; 2.5295x over previous
#include <cuda_runtime.h>
#include <cuda_bf16.h>
#include <cstdint>

#define B 4096
#define D 128
#define TEMP 100.0f
#define SLICES 8
#define JT 4
#define NT 256

#define PITCH 272                     // 256B data + 16B pad: ldmatrix conflict-free
#define SEG_BYTES (128 * PITCH)       // one 128x128 bf16 tile = 34816 B
#define SM_A 0                        // Ah, Al: 2 segs
#define SM_B (2 * SEG_BYTES)          // 2 bufs x (Bh, Bl): 4 segs
#define SM_SQJ (SM_B + 4 * SEG_BYTES) // 512 floats
#define SM_LABJ (SM_SQJ + 2048)       // 512 ints
#define SM_RED (SM_LABJ + 2048)       // 512 floats (d + n)
#define SMEM_SZ (SM_RED + 2048)       // 215040 B

__device__ __align__(16) float g_sq[B];
__device__ int   g_lab[B];
__device__ __align__(16) __nv_bfloat16 g_xh[(size_t)B * D];
__device__ __align__(16) __nv_bfloat16 g_xl[(size_t)B * D];
__device__ float g_pden[SLICES][B];
__device__ float g_pnum[SLICES][B];

__device__ __forceinline__ uint32_t smem_to_u32(const void* p) {
    uint32_t a;
    asm("{ .reg .u64 t; cvta.to.shared.u64 t, %1; cvt.u32.u64 %0, t; }"
        : "=r"(a) : "l"(p));
    return a;
}

#define CP_ASYNC16(dst, src) \
    asm volatile("cp.async.cg.shared.global [%0], [%1], 16;" \
                 :: "r"(dst), "l"(src) : "memory")
#define CP_COMMIT() asm volatile("cp.async.commit_group;" ::: "memory")
#define CP_WAIT0()  asm volatile("cp.async.wait_group 0;" ::: "memory")

#define LDSM_X4(r0, r1, r2, r3, addr) \
    asm volatile("ldmatrix.sync.aligned.m8n8.x4.shared.b16 {%0,%1,%2,%3}, [%4];" \
                 : "=r"(r0), "=r"(r1), "=r"(r2), "=r"(r3) : "r"(addr))

#define MMA16816(c, a, b0, b1) \
    asm volatile("mma.sync.aligned.m16n8k16.row.col.f32.bf16.bf16.f32 " \
                 "{%0,%1,%2,%3}, {%4,%5,%6,%7}, {%8,%9}, {%0,%1,%2,%3};" \
                 : "+f"((c)[0]), "+f"((c)[1]), "+f"((c)[2]), "+f"((c)[3]) \
                 : "r"((a)[0]), "r"((a)[1]), "r"((a)[2]), "r"((a)[3]), \
                   "r"(b0), "r"(b1))

// ---------------------------------------------------------------------------
// Prep: per-row norm + label + bf16 hi/lo split. One warp per row.
// ---------------------------------------------------------------------------
__global__ void snn_prep(const float* __restrict__ x, const int* __restrict__ y) {
    int gw = (blockIdx.x * blockDim.x + threadIdx.x) >> 5;
    int lane = threadIdx.x & 31;
    if (gw >= B) return;
    float4 v = reinterpret_cast<const float4*>(x + (size_t)gw * D)[lane];
    float s = v.x * v.x + v.y * v.y + v.z * v.z + v.w * v.w;
    #pragma unroll
    for (int o = 16; o; o >>= 1) s += __shfl_xor_sync(0xFFFFFFFFu, s, o);
    float vv[4] = {v.x, v.y, v.z, v.w};
    __nv_bfloat16 h[4], l[4];
    #pragma unroll
    for (int i = 0; i < 4; i++) {
        h[i] = __float2bfloat16(vv[i]);
        l[i] = __float2bfloat16(vv[i] - __bfloat162float(h[i]));
    }
    *reinterpret_cast<uint2*>(g_xh + (size_t)gw * D + lane * 4) = *reinterpret_cast<uint2*>(h);
    *reinterpret_cast<uint2*>(g_xl + (size_t)gw * D + lane * 4) = *reinterpret_cast<uint2*>(l);
    if (lane == 0) { g_sq[gw] = s; g_lab[gw] = y[gw]; }
}

// ---------------------------------------------------------------------------
__device__ __forceinline__ void load_B_async(uint32_t sb, int buf, int col0, int tid) {
    #pragma unroll 4
    for (int idx = tid; idx < 4096; idx += NT) {
        int seg = idx >> 11, rem = idx & 2047, r = rem >> 4, g = rem & 15;
        const __nv_bfloat16* src =
            (seg ? g_xl : g_xh) + (size_t)(col0 + r) * D + g * 8;
        uint32_t dst = sb + SM_B + (uint32_t)(buf * 2 + seg) * SEG_BYTES
                       + (uint32_t)(r * PITCH + g * 16);
        CP_ASYNC16(dst, src);
    }
}

// ---------------------------------------------------------------------------
// Main: HMMA Gram tiles (split-bf16, 3 passes) + fused exp/mask epilogue.
// grid (32, 8). 8 warps in 4x2 layout; warp tile = 32 rows x 64 cols.
// ---------------------------------------------------------------------------
__global__ void __launch_bounds__(NT, 1)
snn_main() {
    extern __shared__ char smem[];
    uint32_t sb = smem_to_u32(smem);
    const int tid = threadIdx.x;
    const int lane = tid & 31;
    const int w = tid >> 5, wr = w >> 1, wc = w & 1;
    const int row0 = blockIdx.x * 128;
    const int jg = blockIdx.y;
    const int cbase = jg * (JT * 128);
    const float NEGC = -1.4426950408889634f / TEMP;

    // A strip (hi + lo) async into smem
    #pragma unroll 4
    for (int idx = tid; idx < 4096; idx += NT) {
        int seg = idx >> 11, rem = idx & 2047, r = rem >> 4, g = rem & 15;
        const __nv_bfloat16* src =
            (seg ? g_xl : g_xh) + (size_t)(row0 + r) * D + g * 8;
        uint32_t dst = sb + SM_A + (uint32_t)seg * SEG_BYTES
                       + (uint32_t)(r * PITCH + g * 16);
        CP_ASYNC16(dst, src);
    }
    load_B_async(sb, 0, cbase, tid);

    float* sqj = reinterpret_cast<float*>(smem + SM_SQJ);
    int*   labj = reinterpret_cast<int*>(smem + SM_LABJ);
    for (int idx = tid; idx < JT * 128; idx += NT) {
        sqj[idx]  = g_sq[cbase + idx];
        labj[idx] = g_lab[cbase + idx];
    }
    CP_COMMIT();
    CP_WAIT0();
    __syncthreads();

    // ldmatrix address invariants
    const int grp = lane >> 3, l7 = lane & 7;
    const uint32_t aoff = (uint32_t)((wr * 32 + (grp & 1) * 8 + l7) * PITCH + (grp >> 1) * 16);
    const uint32_t boff = (uint32_t)((wc * 64 + (grp >> 1) * 8 + l7) * PITCH + (grp & 1) * 16);

    // epilogue row invariants (4 rows per thread: mt x row-half)
    const int rbase = lane >> 2, cpair = (lane & 3) * 2;
    float sqi[4]; int labi[4];
    #pragma unroll
    for (int i = 0; i < 4; i++) {
        int gi = row0 + wr * 32 + (i >> 1) * 16 + (i & 1) * 8 + rbase;
        sqi[i] = g_sq[gi];
        labi[i] = g_lab[gi];
    }
    float dsum[4] = {0.f, 0.f, 0.f, 0.f}, nsum[4] = {0.f, 0.f, 0.f, 0.f};

    for (int jj = 0; jj < JT; jj++) {
        const int buf = jj & 1;
        if (jj + 1 < JT)
            load_B_async(sb, buf ^ 1, cbase + (jj + 1) * 128, tid);
        CP_COMMIT();

        float acc[2][8][4];
        #pragma unroll
        for (int mt = 0; mt < 2; mt++)
            #pragma unroll
            for (int nt = 0; nt < 8; nt++)
                #pragma unroll
                for (int e = 0; e < 4; e++) acc[mt][nt][e] = 0.f;

        #pragma unroll
        for (int pass = 0; pass < 3; pass++) {
            // pass 0: Ah*Bh, pass 1: Ah*Bl, pass 2: Al*Bh
            uint32_t abase = sb + SM_A + (pass == 2 ? SEG_BYTES : 0u) + aoff;
            uint32_t bbase = sb + SM_B + (uint32_t)(buf * 2) * SEG_BYTES
                             + (pass == 1 ? SEG_BYTES : 0u) + boff;
            #pragma unroll
            for (int ks = 0; ks < 8; ks++) {
                uint32_t a0[4], a1[4];
                LDSM_X4(a0[0], a0[1], a0[2], a0[3], abase + ks * 32);
                LDSM_X4(a1[0], a1[1], a1[2], a1[3], abase + ks * 32 + 16 * PITCH);
                #pragma unroll
                for (int ntp = 0; ntp < 4; ntp++) {
                    uint32_t b[4];
                    LDSM_X4(b[0], b[1], b[2], b[3],
                            bbase + ks * 32 + ntp * 16 * PITCH);
                    MMA16816(acc[0][2 * ntp],     a0, b[0], b[1]);
                    MMA16816(acc[0][2 * ntp + 1], a0, b[2], b[3]);
                    MMA16816(acc[1][2 * ntp],     a1, b[0], b[1]);
                    MMA16816(acc[1][2 * ntp + 1], a1, b[2], b[3]);
                }
            }
        }

        // fused epilogue: dist -> exp -> masked sums (registers only)
        #pragma unroll
        for (int mt = 0; mt < 2; mt++)
            #pragma unroll
            for (int nt = 0; nt < 8; nt++)
                #pragma unroll
                for (int e = 0; e < 4; e++) {
                    int half = e >> 1;
                    int i = mt * 2 + half;
                    int gi = row0 + wr * 32 + mt * 16 + half * 8 + rbase;
                    int lc = jj * 128 + wc * 64 + nt * 8 + cpair + (e & 1);
                    float dist = sqi[i] + sqj[lc] - 2.f * acc[mt][nt][e];
                    dist = fmaxf(dist, 0.f);
                    float ev = exp2f(dist * NEGC);
                    int col = cbase + lc;
                    if (gi == col) ev = 1.f;
                    dsum[i] += ev;
                    nsum[i] += (labi[i] == labj[lc] && gi != col) ? ev : 0.f;
                }

        CP_WAIT0();
        __syncthreads();
    }

    // quad reduce (lanes sharing a row), then cross-warp-column reduce in smem
    #pragma unroll
    for (int i = 0; i < 4; i++) {
        dsum[i] += __shfl_xor_sync(0xFFFFFFFFu, dsum[i], 1);
        dsum[i] += __shfl_xor_sync(0xFFFFFFFFu, dsum[i], 2);
        nsum[i] += __shfl_xor_sync(0xFFFFFFFFu, nsum[i], 1);
        nsum[i] += __shfl_xor_sync(0xFFFFFFFFu, nsum[i], 2);
    }
    float* dred = reinterpret_cast<float*>(smem + SM_RED);  // [2][128]
    float* nred = dred + 256;
    if ((lane & 3) == 0) {
        #pragma unroll
        for (int i = 0; i < 4; i++) {
            int rloc = wr * 32 + (i >> 1) * 16 + (i & 1) * 8 + rbase;
            dred[wc * 128 + rloc] = dsum[i];
            nred[wc * 128 + rloc] = nsum[i];
        }
    }
    __syncthreads();
    if (tid < 128) {
        g_pden[jg][row0 + tid] = dred[tid] + dred[128 + tid];
        g_pnum[jg][row0 + tid] = nred[tid] + nred[128 + tid];
    }
}

// ---------------------------------------------------------------------------
// Finalize: combine slice partials, mean(-log(num/den))
// ---------------------------------------------------------------------------
__global__ void snn_finalize(float* __restrict__ out) {
    __shared__ float sred[NT];
    int tid = threadIdx.x;
    float s = 0.f;
    for (int i = tid; i < B; i += NT) {
        float den = 0.f, num = 0.f;
        #pragma unroll
        for (int p = 0; p < SLICES; p++) { den += g_pden[p][i]; num += g_pnum[p][i]; }
        s += logf(den) - logf(num);
    }
    sred[tid] = s;
    __syncthreads();
    for (int off = NT / 2; off > 0; off >>= 1) {
        if (tid < off) sred[tid] += sred[tid + off];
        __syncthreads();
    }
    if (tid == 0) out[0] = sred[0] / (float)B;
}

// ---------------------------------------------------------------------------
extern "C" void kernel_launch(void* const* d_in, const int* in_sizes, int n_in,
                              void* d_out, int out_size) {
    const float* x = (const float*)d_in[0];
    const int*   y = (const int*)d_in[1];
    float* out = (float*)d_out;

    cudaFuncSetAttribute(snn_main, cudaFuncAttributeMaxDynamicSharedMemorySize, SMEM_SZ);

    snn_prep<<<B / 8, NT>>>(x, y);               // 512 blocks, warp per row
    snn_main<<<dim3(B / 128, SLICES), NT, SMEM_SZ>>>();
    snn_finalize<<<1, NT>>>(out);
}

// round 5
// speedup vs baseline: 2.6077x; 1.0309x over previous
#include <cuda_runtime.h>
#include <cuda_bf16.h>
#include <cstdint>

#define B 4096
#define D 128
#define TEMP 100.0f
#define NT 512
#define NBLK 32                       // 128-row blocks
#define NTILES (NBLK * (NBLK + 1) / 2)  // 528

#define PITCH 272                     // 256B row + 16B pad (ldmatrix conflict-free)
#define SEG 34816                     // 128 * PITCH
#define SM_AH 0
#define SM_AL SEG
#define SM_BH (2 * SEG)
#define SM_BL (3 * SEG)
#define SM_META (4 * SEG)             // sqr[128] sqc[128] labr[128] labc[128]
#define SMEM_SZ (SM_META + 2048)      // 141312

__device__ __align__(16) float g_sq[B];
__device__ int   g_lab[B];
__device__ __align__(16) __nv_bfloat16 g_xh[(size_t)B * D];
__device__ __align__(16) __nv_bfloat16 g_xl[(size_t)B * D];
__device__ float g_pd[NBLK][B];       // slot s, row i : unique writer per launch
__device__ float g_pn[NBLK][B];

__device__ __forceinline__ uint32_t smem_to_u32(const void* p) {
    uint32_t a;
    asm("{ .reg .u64 t; cvta.to.shared.u64 t, %1; cvt.u32.u64 %0, t; }"
        : "=r"(a) : "l"(p));
    return a;
}
#define CP_ASYNC16(dst, src) \
    asm volatile("cp.async.cg.shared.global [%0], [%1], 16;" \
                 :: "r"(dst), "l"(src) : "memory")
#define CP_COMMIT() asm volatile("cp.async.commit_group;" ::: "memory")
#define CP_WAIT(n)  asm volatile("cp.async.wait_group %0;" :: "n"(n) : "memory")
#define LDSM_X4(r0, r1, r2, r3, addr) \
    asm volatile("ldmatrix.sync.aligned.m8n8.x4.shared.b16 {%0,%1,%2,%3}, [%4];" \
                 : "=r"(r0), "=r"(r1), "=r"(r2), "=r"(r3) : "r"(addr))
#define MMA16816(c, a, b0, b1) \
    asm volatile("mma.sync.aligned.m16n8k16.row.col.f32.bf16.bf16.f32 " \
                 "{%0,%1,%2,%3}, {%4,%5,%6,%7}, {%8,%9}, {%0,%1,%2,%3};" \
                 : "+f"((c)[0]), "+f"((c)[1]), "+f"((c)[2]), "+f"((c)[3]) \
                 : "r"((a)[0]), "r"((a)[1]), "r"((a)[2]), "r"((a)[3]), \
                   "r"(b0), "r"(b1))

// ---------------------------------------------------------------------------
// Prep: per-row norm + label + bf16 hi/lo split. One warp per row.
// ---------------------------------------------------------------------------
__global__ void snn_prep(const float* __restrict__ x, const int* __restrict__ y) {
    int gw = (blockIdx.x * blockDim.x + threadIdx.x) >> 5;
    int lane = threadIdx.x & 31;
    if (gw >= B) return;
    float4 v = reinterpret_cast<const float4*>(x + (size_t)gw * D)[lane];
    float s = v.x * v.x + v.y * v.y + v.z * v.z + v.w * v.w;
    #pragma unroll
    for (int o = 16; o; o >>= 1) s += __shfl_xor_sync(0xFFFFFFFFu, s, o);
    float vv[4] = {v.x, v.y, v.z, v.w};
    __nv_bfloat16 h[4], l[4];
    #pragma unroll
    for (int i = 0; i < 4; i++) {
        h[i] = __float2bfloat16(vv[i]);
        l[i] = __float2bfloat16(vv[i] - __bfloat162float(h[i]));
    }
    *reinterpret_cast<uint2*>(g_xh + (size_t)gw * D + lane * 4) = *reinterpret_cast<uint2*>(h);
    *reinterpret_cast<uint2*>(g_xl + (size_t)gw * D + lane * 4) = *reinterpret_cast<uint2*>(l);
    if (lane == 0) { g_sq[gw] = s; g_lab[gw] = y[gw]; }
}

// ---------------------------------------------------------------------------
__device__ __forceinline__ void load_seg(uint32_t dst_base,
                                         const __nv_bfloat16* src, int row0, int tid) {
    #pragma unroll
    for (int idx = tid; idx < 2048; idx += NT) {
        int r = idx >> 4, g = idx & 15;
        CP_ASYNC16(dst_base + (uint32_t)(r * PITCH + g * 16),
                   src + (size_t)(row0 + r) * D + g * 8);
    }
}

// One K=128 MMA pass: A-operand tile at abase, B-operand tile at bbase.
__device__ __forceinline__ void mma_pass(float acc[2][4][4],
                                         uint32_t abase, uint32_t bbase) {
    #pragma unroll
    for (int ks = 0; ks < 8; ks++) {
        uint32_t a0[4], a1[4];
        LDSM_X4(a0[0], a0[1], a0[2], a0[3], abase + ks * 32);
        LDSM_X4(a1[0], a1[1], a1[2], a1[3], abase + ks * 32 + 16 * PITCH);
        #pragma unroll
        for (int np = 0; np < 2; np++) {
            uint32_t b[4];
            LDSM_X4(b[0], b[1], b[2], b[3], bbase + ks * 32 + np * 16 * PITCH);
            MMA16816(acc[0][2 * np],     a0, b[0], b[1]);
            MMA16816(acc[0][2 * np + 1], a0, b[2], b[3]);
            MMA16816(acc[1][2 * np],     a1, b[0], b[1]);
            MMA16816(acc[1][2 * np + 1], a1, b[2], b[3]);
        }
    }
}

// ---------------------------------------------------------------------------
// Main: one 128x128 Gram tile per CTA, upper triangle only (528 CTAs).
// 16 warps in 4x4 layout, warp tile 32x32. Split-bf16: Ah*Bh + Ah*Bl + Al*Bh.
// Off-diagonal tiles emit BOTH row sums (block bi) and col sums (block bj).
// ---------------------------------------------------------------------------
__global__ void __launch_bounds__(NT, 1)
snn_main() {
    extern __shared__ char smem[];
    uint32_t sb = smem_to_u32(smem);
    const int tid = threadIdx.x;
    const int lane = tid & 31;
    const int w = tid >> 5, wr = w >> 2, wc = w & 3;
    const float NEGC = -1.4426950408889634f / TEMP;

    // triangle decode: blockIdx.x -> (bi, bj), bi <= bj
    int t = blockIdx.x, bi = 0;
    while (t >= NBLK - bi) { t -= NBLK - bi; bi++; }
    const int bj = bi + t;
    const bool diag = (bi == bj);
    const int row0 = bi * 128, col0 = bj * 128;

    // async loads with incremental groups
    load_seg(sb + SM_AH, g_xh, row0, tid);
    if (!diag) load_seg(sb + SM_BH, g_xh, col0, tid);
    CP_COMMIT();                                   // G1: Ah (+Bh)
    if (!diag) load_seg(sb + SM_BL, g_xl, col0, tid);
    CP_COMMIT();                                   // G2: Bl (empty if diag)
    load_seg(sb + SM_AL, g_xl, row0, tid);
    CP_COMMIT();                                   // G3: Al

    float* sqr = reinterpret_cast<float*>(smem + SM_META);
    float* sqc = sqr + 128;
    int*   labr = reinterpret_cast<int*>(sqc + 128);
    int*   labc = labr + 128;
    for (int i = tid; i < 128; i += NT) {
        sqr[i] = g_sq[row0 + i];  labr[i] = g_lab[row0 + i];
        sqc[i] = g_sq[col0 + i];  labc[i] = g_lab[col0 + i];
    }

    // ldmatrix per-lane offsets (R4-verified fragment addressing)
    const int grp = lane >> 3, l7 = lane & 7;
    const uint32_t aoff = (uint32_t)((wr * 32 + (grp & 1) * 8 + l7) * PITCH + (grp >> 1) * 16);
    const uint32_t boff = (uint32_t)((wc * 32 + (grp >> 1) * 8 + l7) * PITCH + (grp & 1) * 16);

    float acc[2][4][4];
    #pragma unroll
    for (int mt = 0; mt < 2; mt++)
        #pragma unroll
        for (int nt = 0; nt < 4; nt++)
            #pragma unroll
            for (int e = 0; e < 4; e++) acc[mt][nt][e] = 0.f;

    const uint32_t bh_base = diag ? (sb + SM_AH) : (sb + SM_BH);

    CP_WAIT(2);
    __syncthreads();
    mma_pass(acc, sb + SM_AH + aoff, bh_base + boff);          // P0: Ah*Bh
    if (diag) {
        CP_WAIT(0);
        __syncthreads();
        mma_pass(acc, sb + SM_AH + aoff, sb + SM_AL + boff);   // P1: Ah*Al
        mma_pass(acc, sb + SM_AL + aoff, sb + SM_AH + boff);   // P2: Al*Ah
    } else {
        CP_WAIT(1);
        __syncthreads();
        mma_pass(acc, sb + SM_AH + aoff, sb + SM_BL + boff);   // P1: Ah*Bl
        CP_WAIT(0);
        __syncthreads();
        mma_pass(acc, sb + SM_AL + aoff, sb + SM_BH + boff);   // P2: Al*Bh
    }

    // ---------------- epilogue: dist -> exp -> masked row & col sums --------
    const int rbase = lane >> 2, cpair = (lane & 3) * 2;
    float sqi[4]; int labi[4];
    #pragma unroll
    for (int i = 0; i < 4; i++) {
        int rloc = wr * 32 + (i >> 1) * 16 + (i & 1) * 8 + rbase;
        sqi[i] = sqr[rloc];  labi[i] = labr[rloc];
    }
    float sqjt[8]; int labjt[8];
    #pragma unroll
    for (int k = 0; k < 8; k++) {
        int lc = wc * 32 + (k >> 1) * 8 + cpair + (k & 1);
        sqjt[k] = sqc[lc];  labjt[k] = labc[lc];
    }

    float rs_d[4] = {0.f, 0.f, 0.f, 0.f}, rs_n[4] = {0.f, 0.f, 0.f, 0.f};
    float cs_d[8] = {0.f, 0.f, 0.f, 0.f, 0.f, 0.f, 0.f, 0.f};
    float cs_n[8] = {0.f, 0.f, 0.f, 0.f, 0.f, 0.f, 0.f, 0.f};

    #pragma unroll
    for (int mt = 0; mt < 2; mt++)
        #pragma unroll
        for (int nt = 0; nt < 4; nt++)
            #pragma unroll
            for (int e = 0; e < 4; e++) {
                int half = e >> 1, p = e & 1;
                int i = mt * 2 + half, k = nt * 2 + p;
                int gi  = row0 + wr * 32 + mt * 16 + half * 8 + rbase;
                int col = col0 + wc * 32 + nt * 8 + cpair + p;
                float dist = sqi[i] + sqjt[k] - 2.f * acc[mt][nt][e];
                dist = fmaxf(dist, 0.f);
                float ev = exp2f(dist * NEGC);
                bool self = (gi == col);
                if (self) ev = 1.f;
                bool same = (labi[i] == labjt[k]) && !self;
                float nv = same ? ev : 0.f;
                rs_d[i] += ev;  rs_n[i] += nv;
                cs_d[k] += ev;  cs_n[k] += nv;
            }

    // intra-warp reductions
    #pragma unroll
    for (int i = 0; i < 4; i++) {
        rs_d[i] += __shfl_xor_sync(0xFFFFFFFFu, rs_d[i], 1);
        rs_d[i] += __shfl_xor_sync(0xFFFFFFFFu, rs_d[i], 2);
        rs_n[i] += __shfl_xor_sync(0xFFFFFFFFu, rs_n[i], 1);
        rs_n[i] += __shfl_xor_sync(0xFFFFFFFFu, rs_n[i], 2);
    }
    #pragma unroll
    for (int k = 0; k < 8; k++) {
        cs_d[k] += __shfl_xor_sync(0xFFFFFFFFu, cs_d[k], 4);
        cs_d[k] += __shfl_xor_sync(0xFFFFFFFFu, cs_d[k], 8);
        cs_d[k] += __shfl_xor_sync(0xFFFFFFFFu, cs_d[k], 16);
        cs_n[k] += __shfl_xor_sync(0xFFFFFFFFu, cs_n[k], 4);
        cs_n[k] += __shfl_xor_sync(0xFFFFFFFFu, cs_n[k], 8);
        cs_n[k] += __shfl_xor_sync(0xFFFFFFFFu, cs_n[k], 16);
    }

    // cross-warp reduction in reused tile smem
    __syncthreads();   // all LDSM reads of tiles complete
    float* rowD = reinterpret_cast<float*>(smem);          // [4][128]
    float* rowN = rowD + 512;
    float* colD = rowN + 512;
    float* colN = colD + 512;
    if ((lane & 3) == 0) {
        #pragma unroll
        for (int i = 0; i < 4; i++) {
            int rloc = wr * 32 + (i >> 1) * 16 + (i & 1) * 8 + rbase;
            rowD[wc * 128 + rloc] = rs_d[i];
            rowN[wc * 128 + rloc] = rs_n[i];
        }
    }
    if (lane < 4) {
        #pragma unroll
        for (int k = 0; k < 8; k++) {
            int cloc = wc * 32 + (k >> 1) * 8 + lane * 2 + (k & 1);
            colD[wr * 128 + cloc] = cs_d[k];
            colN[wr * 128 + cloc] = cs_n[k];
        }
    }
    __syncthreads();
    if (tid < 128) {
        g_pd[bj][row0 + tid] = rowD[tid] + rowD[128 + tid] + rowD[256 + tid] + rowD[384 + tid];
        g_pn[bj][row0 + tid] = rowN[tid] + rowN[128 + tid] + rowN[256 + tid] + rowN[384 + tid];
    } else if (tid < 256 && !diag) {
        int c = tid - 128;
        g_pd[bi][col0 + c] = colD[c] + colD[128 + c] + colD[256 + c] + colD[384 + c];
        g_pn[bi][col0 + c] = colN[c] + colN[128 + c] + colN[256 + c] + colN[384 + c];
    }
}

// ---------------------------------------------------------------------------
// Finalize: combine 32 slot partials, mean(-log(num/den))
// ---------------------------------------------------------------------------
__global__ void snn_finalize(float* __restrict__ out) {
    __shared__ float sred[256];
    int tid = threadIdx.x;
    float s = 0.f;
    for (int i = tid; i < B; i += 256) {
        float den = 0.f, num = 0.f;
        #pragma unroll
        for (int p = 0; p < NBLK; p++) { den += g_pd[p][i]; num += g_pn[p][i]; }
        s += logf(den) - logf(num);
    }
    sred[tid] = s;
    __syncthreads();
    for (int off = 128; off > 0; off >>= 1) {
        if (tid < off) sred[tid] += sred[tid + off];
        __syncthreads();
    }
    if (tid == 0) out[0] = sred[0] / (float)B;
}

// ---------------------------------------------------------------------------
extern "C" void kernel_launch(void* const* d_in, const int* in_sizes, int n_in,
                              void* d_out, int out_size) {
    const float* x = (const float*)d_in[0];
    const int*   y = (const int*)d_in[1];
    float* out = (float*)d_out;

    cudaFuncSetAttribute(snn_main, cudaFuncAttributeMaxDynamicSharedMemorySize, SMEM_SZ);

    snn_prep<<<B / 8, 256>>>(x, y);
    snn_main<<<NTILES, NT, SMEM_SZ>>>();
    snn_finalize<<<1, 256>>>(out);
}

// round 6
// speedup vs baseline: 3.5527x; 1.3624x over previous
#include <cuda_runtime.h>
#include <cuda_bf16.h>
#include <cstdint>

#define B 4096
#define D 128
#define TEMP 100.0f
#define NT 512
#define NBLK 16                        // 256-row blocks
#define NTILES (NBLK * (NBLK + 1) / 2) // 136
#define BS (B * 64)                    // elems per plane (B rows x 128B)

// smem map
#define SM_A     0                     // Ah0,Ah1,Al0,Al1 : 4 x 32768
#define SM_B     131072                // 2 bufs x (Bh0,Bh1,Bl0,Bl1 : 4 x 8192)
#define SM_META  196608                // sqr[256] sqc[256] labr[256] labc[256]
#define SM_RED   200704                // rowD[512] rowN[512] colD[512] colN[512]
#define SM_MB    208896                // mbarA, mbarB0, mbarB1
#define SMEM_SZ  209024

// gmem: 4 planes (h0,h1,l0,l1), each row 128B, SW128 pre-swizzled per 1024B blk
__device__ __align__(1024) __nv_bfloat16 g_xs[4 * BS];
__device__ __align__(16) float g_sq[B];
__device__ int   g_lab[B];
__device__ float g_pd[NBLK][B];
__device__ float g_pn[NBLK][B];
__device__ float g_part[16];

__device__ __forceinline__ uint32_t smem_to_u32(const void* p) {
    uint32_t a;
    asm("{ .reg .u64 t; cvta.to.shared.u64 t, %1; cvt.u32.u64 %0, t; }"
        : "=r"(a) : "l"(p));
    return a;
}
__device__ __forceinline__ uint32_t swz(uint32_t x) { return x ^ ((x >> 3) & 0x70); }

#define MBAR_INIT(m, c) \
    asm volatile("mbarrier.init.shared.b64 [%0], %1;" \
                 :: "r"((uint32_t)(m)), "r"((uint32_t)(c)) : "memory")
#define MBAR_EXPECT(m, n) \
    asm volatile("mbarrier.arrive.expect_tx.shared.b64 _, [%0], %1;" \
                 :: "r"((uint32_t)(m)), "r"((uint32_t)(n)) : "memory")
#define MBAR_WAIT(m, par) do { \
    uint32_t _m = (uint32_t)(m); uint32_t _p = (uint32_t)(par); uint32_t _d; \
    asm volatile("{\n\t.reg .pred p;\n\t" \
        "mbarrier.try_wait.parity.acquire.cta.shared::cta.b64 p, [%1], %2;\n\t" \
        "selp.b32 %0, 1, 0, p;\n\t}" : "=r"(_d) : "r"(_m), "r"(_p) : "memory"); \
    if (!_d) { \
        asm volatile("{\n\t.reg .pred P1;\n\t" \
            "WL_%=:\n\t" \
            "mbarrier.try_wait.parity.acquire.cta.shared::cta.b64 P1, [%0], %1, 0x989680;\n\t" \
            "@P1 bra.uni WD_%=;\n\tbra.uni WL_%=;\n\tWD_%=:\n\t}" \
            :: "r"(_m), "r"(_p) : "memory"); \
    } } while (0)

__device__ __forceinline__ void bulk_cp(uint32_t dst, const void* src,
                                        uint32_t bytes, uint32_t mbar) {
    asm volatile(
        "cp.async.bulk.shared::cluster.global.mbarrier::complete_tx::bytes "
        "[%0], [%1], %2, [%3];"
        :: "r"(dst), "l"(src), "r"(bytes), "r"(mbar) : "memory");
}

#define LDSM_X4(r0, r1, r2, r3, addr) \
    asm volatile("ldmatrix.sync.aligned.m8n8.x4.shared.b16 {%0,%1,%2,%3}, [%4];" \
                 : "=r"(r0), "=r"(r1), "=r"(r2), "=r"(r3) : "r"(addr))
#define MMA16816(c, a, b0, b1) \
    asm volatile("mma.sync.aligned.m16n8k16.row.col.f32.bf16.bf16.f32 " \
                 "{%0,%1,%2,%3}, {%4,%5,%6,%7}, {%8,%9}, {%0,%1,%2,%3};" \
                 : "+f"((c)[0]), "+f"((c)[1]), "+f"((c)[2]), "+f"((c)[3]) \
                 : "r"((a)[0]), "r"((a)[1]), "r"((a)[2]), "r"((a)[3]), \
                   "r"(b0), "r"(b1))

// ---------------------------------------------------------------------------
// Prep: per-row norm + label + bf16 hi/lo split into pre-swizzled planes.
// One warp per row; lane owns 4 consecutive k (8B, swizzle-granule safe).
// ---------------------------------------------------------------------------
__global__ void snn_prep(const float* __restrict__ x, const int* __restrict__ y) {
    int gw = (blockIdx.x * blockDim.x + threadIdx.x) >> 5;
    int lane = threadIdx.x & 31;
    if (gw >= B) return;
    float4 v = reinterpret_cast<const float4*>(x + (size_t)gw * D)[lane];
    float s = v.x * v.x + v.y * v.y + v.z * v.z + v.w * v.w;
    #pragma unroll
    for (int o = 16; o; o >>= 1) s += __shfl_xor_sync(0xFFFFFFFFu, s, o);
    float vv[4] = {v.x, v.y, v.z, v.w};
    __nv_bfloat16 h[4], l[4];
    #pragma unroll
    for (int i = 0; i < 4; i++) {
        h[i] = __float2bfloat16(vv[i]);
        l[i] = __float2bfloat16(vv[i] - __bfloat162float(h[i]));
    }
    int k = lane * 4;
    int hseg = k >> 6;                               // 0 or 1
    uint32_t byte = (uint32_t)gw * 128 + (k & 63) * 2;
    uint32_t sby = swz(byte);
    char* base = reinterpret_cast<char*>(g_xs);
    *reinterpret_cast<uint2*>(base + (size_t)hseg * (BS * 2) + sby) =
        *reinterpret_cast<uint2*>(h);
    *reinterpret_cast<uint2*>(base + (size_t)(hseg + 2) * (BS * 2) + sby) =
        *reinterpret_cast<uint2*>(l);
    if (lane == 0) { g_sq[gw] = s; g_lab[gw] = y[gw]; }
}

// ---------------------------------------------------------------------------
// One K=128 MMA pass over a 32x32 warp tile.
// abase/bbase: plane-0 bases; plane-1 at +astride/+bstride. pa/pb: per-lane
// (row*128 + colsel*16) pre-offsets; swizzle applied per k-step.
// ---------------------------------------------------------------------------
__device__ __forceinline__ void mma_pass(float acc[2][4][4],
                                         uint32_t abase, uint32_t bbase,
                                         uint32_t bstride,
                                         uint32_t pa, uint32_t pb) {
    #pragma unroll
    for (int ks = 0; ks < 8; ks++) {
        const uint32_t koff = (ks & 3) * 32;
        const uint32_t ka = abase + (ks >> 2) * 32768;
        const uint32_t kb = bbase + (ks >> 2) * bstride;
        uint32_t a0[4], a1[4], b0[4], b1[4];
        LDSM_X4(a0[0], a0[1], a0[2], a0[3], ka + swz(pa + koff));
        LDSM_X4(a1[0], a1[1], a1[2], a1[3], ka + swz(pa + 2048 + koff));
        LDSM_X4(b0[0], b0[1], b0[2], b0[3], kb + swz(pb + koff));
        LDSM_X4(b1[0], b1[1], b1[2], b1[3], kb + swz(pb + 2048 + koff));
        MMA16816(acc[0][0], a0, b0[0], b0[1]);
        MMA16816(acc[0][1], a0, b0[2], b0[3]);
        MMA16816(acc[0][2], a0, b1[0], b1[1]);
        MMA16816(acc[0][3], a0, b1[2], b1[3]);
        MMA16816(acc[1][0], a1, b0[0], b0[1]);
        MMA16816(acc[1][1], a1, b0[2], b0[3]);
        MMA16816(acc[1][2], a1, b1[0], b1[1]);
        MMA16816(acc[1][3], a1, b1[2], b1[3]);
    }
}

// ---------------------------------------------------------------------------
// Main: one 256x256 Gram tile per CTA, triangle of 16 blocks (136 CTAs).
// A (hi+lo) resident; B streamed in 64-row chunks, double-buffered bulk-async.
// 16 warps 8x2, warp tile 32x32. Split-bf16: Ah*Bh + Ah*Bl + Al*Bh.
// ---------------------------------------------------------------------------
__global__ void __launch_bounds__(NT, 1)
snn_main() {
    extern __shared__ char smem[];
    uint32_t sb = smem_to_u32(smem);
    const int tid = threadIdx.x;
    const int lane = tid & 31;
    const int w = tid >> 5, wr = w >> 1, wc = w & 1;
    const int grp = lane >> 3, l7 = lane & 7;
    const float NEGC = -1.4426950408889634f / TEMP;

    int t = blockIdx.x, bi = 0;
    while (t >= NBLK - bi) { t -= NBLK - bi; bi++; }
    const int bj = bi + t;
    const bool diag = (bi == bj);
    const int row0 = bi * 256, col0 = bj * 256;

    const uint32_t mbA  = sb + SM_MB;
    const uint32_t mbB0 = sb + SM_MB + 8;
    const uint32_t mbB1 = sb + SM_MB + 16;

    if (tid == 0) { MBAR_INIT(mbA, 1); MBAR_INIT(mbB0, 1); MBAR_INIT(mbB1, 1); }
    __syncthreads();

    const char* gx = reinterpret_cast<const char*>(g_xs);
    if (tid == 0) {
        MBAR_EXPECT(mbA, 131072);
        #pragma unroll
        for (int s = 0; s < 4; s++)
            bulk_cp(sb + SM_A + s * 32768,
                    gx + (size_t)s * (BS * 2) + (size_t)row0 * 128, 32768, mbA);
        if (!diag) {
            MBAR_EXPECT(mbB0, 32768);
            #pragma unroll
            for (int s = 0; s < 4; s++)
                bulk_cp(sb + SM_B + s * 8192,
                        gx + (size_t)s * (BS * 2) + (size_t)col0 * 128, 8192, mbB0);
        }
    }

    float* sqr  = reinterpret_cast<float*>(smem + SM_META);
    float* sqc  = sqr + 256;
    int*   labr = reinterpret_cast<int*>(sqc + 256);
    int*   labc = labr + 256;
    {
        int i = tid;
        if (i < 256)      { sqr[i] = g_sq[row0 + i];        labr[i] = g_lab[row0 + i]; }
        else              { sqc[i - 256] = g_sq[col0 + i - 256];
                            labc[i - 256] = g_lab[col0 + i - 256]; }
    }
    __syncthreads();

    const uint32_t pa = (uint32_t)((wr * 32 + (grp & 1) * 8 + l7) * 128 + (grp >> 1) * 16);
    const uint32_t pb = (uint32_t)((wc * 32 + (grp >> 1) * 8 + l7) * 128 + (grp & 1) * 16);
    const int rbase = lane >> 2, cpair = (lane & 3) * 2;

    float sqi[4]; int labi[4];
    #pragma unroll
    for (int i = 0; i < 4; i++) {
        int rloc = wr * 32 + (i >> 1) * 16 + (i & 1) * 8 + rbase;
        sqi[i] = sqr[rloc];  labi[i] = labr[rloc];
    }
    float rs_d[4] = {0.f, 0.f, 0.f, 0.f}, rs_n[4] = {0.f, 0.f, 0.f, 0.f};

    float* rowD = reinterpret_cast<float*>(smem + SM_RED);
    float* rowN = rowD + 512;
    float* colD = rowN + 512;
    float* colN = colD + 512;

    MBAR_WAIT(mbA, 0);

    for (int c = 0; c < 4; c++) {
        if (!diag) {
            if (tid == 0 && c < 3) {
                uint32_t mb = (c & 1) ? mbB0 : mbB1;     // buf (c+1)&1
                MBAR_EXPECT(mb, 32768);
                #pragma unroll
                for (int s = 0; s < 4; s++)
                    bulk_cp(sb + SM_B + (uint32_t)(((c + 1) & 1) * 32768 + s * 8192),
                            gx + (size_t)s * (BS * 2)
                               + (size_t)(col0 + (c + 1) * 64) * 128, 8192, mb);
            }
            MBAR_WAIT((c & 1) ? mbB1 : mbB0, (c >> 1) & 1);
        }

        float acc[2][4][4];
        #pragma unroll
        for (int mt = 0; mt < 2; mt++)
            #pragma unroll
            for (int nt = 0; nt < 4; nt++)
                #pragma unroll
                for (int e = 0; e < 4; e++) acc[mt][nt][e] = 0.f;

        uint32_t aH = sb + SM_A, aL = sb + SM_A + 65536;
        uint32_t bH, bL, bstr;
        if (diag) { bH = aH + c * 8192;  bL = aL + c * 8192;  bstr = 32768; }
        else {
            uint32_t bb = sb + SM_B + (uint32_t)((c & 1) * 32768);
            bH = bb;  bL = bb + 16384;  bstr = 8192;
        }
        mma_pass(acc, aH, bH, bstr, pa, pb);   // Ah*Bh
        mma_pass(acc, aH, bL, bstr, pa, pb);   // Ah*Bl
        mma_pass(acc, aL, bH, bstr, pa, pb);   // Al*Bh

        // ---- epilogue for this 256x64 chunk ----
        float sqjt[8]; int labjt[8];
        #pragma unroll
        for (int k = 0; k < 8; k++) {
            int cloc = wc * 32 + (k >> 1) * 8 + cpair + (k & 1);
            sqjt[k] = sqc[c * 64 + cloc];  labjt[k] = labc[c * 64 + cloc];
        }
        float cs_d[8] = {0,0,0,0,0,0,0,0}, cs_n[8] = {0,0,0,0,0,0,0,0};

        #pragma unroll
        for (int mt = 0; mt < 2; mt++)
            #pragma unroll
            for (int nt = 0; nt < 4; nt++)
                #pragma unroll
                for (int e = 0; e < 4; e++) {
                    int half = e >> 1, p = e & 1;
                    int i = mt * 2 + half, k = nt * 2 + p;
                    int gi  = row0 + wr * 32 + mt * 16 + half * 8 + rbase;
                    int col = col0 + c * 64 + wc * 32 + nt * 8 + cpair + p;
                    float dist = sqi[i] + sqjt[k] - 2.f * acc[mt][nt][e];
                    dist = fmaxf(dist, 0.f);
                    float ev = exp2f(dist * NEGC);
                    bool self = (gi == col);
                    if (self) ev = 1.f;
                    float nv = (labi[i] == labjt[k] && !self) ? ev : 0.f;
                    rs_d[i] += ev;  rs_n[i] += nv;
                    cs_d[k] += ev;  cs_n[k] += nv;
                }

        if (!diag) {
            #pragma unroll
            for (int k = 0; k < 8; k++) {
                cs_d[k] += __shfl_xor_sync(0xFFFFFFFFu, cs_d[k], 4);
                cs_d[k] += __shfl_xor_sync(0xFFFFFFFFu, cs_d[k], 8);
                cs_d[k] += __shfl_xor_sync(0xFFFFFFFFu, cs_d[k], 16);
                cs_n[k] += __shfl_xor_sync(0xFFFFFFFFu, cs_n[k], 4);
                cs_n[k] += __shfl_xor_sync(0xFFFFFFFFu, cs_n[k], 8);
                cs_n[k] += __shfl_xor_sync(0xFFFFFFFFu, cs_n[k], 16);
            }
            __syncthreads();
            if (lane < 4) {
                #pragma unroll
                for (int k = 0; k < 8; k++) {
                    int cloc = wc * 32 + (k >> 1) * 8 + lane * 2 + (k & 1);
                    colD[wr * 64 + cloc] = cs_d[k];
                    colN[wr * 64 + cloc] = cs_n[k];
                }
            }
            __syncthreads();
            if (tid < 64) {
                float sd = 0.f, sn = 0.f;
                #pragma unroll
                for (int s = 0; s < 8; s++) { sd += colD[s * 64 + tid]; sn += colN[s * 64 + tid]; }
                g_pd[bi][col0 + c * 64 + tid] = sd;
                g_pn[bi][col0 + c * 64 + tid] = sn;
            }
        }
        __syncthreads();
    }

    // ---- row-sum cross-warp reduce + store ----
    #pragma unroll
    for (int i = 0; i < 4; i++) {
        rs_d[i] += __shfl_xor_sync(0xFFFFFFFFu, rs_d[i], 1);
        rs_d[i] += __shfl_xor_sync(0xFFFFFFFFu, rs_d[i], 2);
        rs_n[i] += __shfl_xor_sync(0xFFFFFFFFu, rs_n[i], 1);
        rs_n[i] += __shfl_xor_sync(0xFFFFFFFFu, rs_n[i], 2);
    }
    if ((lane & 3) == 0) {
        #pragma unroll
        for (int i = 0; i < 4; i++) {
            int rloc = wr * 32 + (i >> 1) * 16 + (i & 1) * 8 + rbase;
            rowD[wc * 256 + rloc] = rs_d[i];
            rowN[wc * 256 + rloc] = rs_n[i];
        }
    }
    __syncthreads();
    if (tid < 256) {
        g_pd[bj][row0 + tid] = rowD[tid] + rowD[256 + tid];
        g_pn[bj][row0 + tid] = rowN[tid] + rowN[256 + tid];
    }
}

// ---------------------------------------------------------------------------
// Finalize stage A: per-row loss, 16 blocks. Stage B: mean.
// ---------------------------------------------------------------------------
__global__ void snn_fin1() {
    __shared__ float sred[256];
    int i = blockIdx.x * 256 + threadIdx.x;
    float den = 0.f, num = 0.f;
    #pragma unroll
    for (int p = 0; p < NBLK; p++) { den += g_pd[p][i]; num += g_pn[p][i]; }
    float s = logf(den) - logf(num);
    sred[threadIdx.x] = s;
    __syncthreads();
    for (int off = 128; off > 0; off >>= 1) {
        if (threadIdx.x < off) sred[threadIdx.x] += sred[threadIdx.x + off];
        __syncthreads();
    }
    if (threadIdx.x == 0) g_part[blockIdx.x] = sred[0];
}

__global__ void snn_fin2(float* __restrict__ out) {
    int tid = threadIdx.x;
    float s = (tid < 16) ? g_part[tid] : 0.f;
    #pragma unroll
    for (int o = 16; o; o >>= 1) s += __shfl_xor_sync(0xFFFFFFFFu, s, o);
    if (tid == 0) out[0] = s / (float)B;
}

// ---------------------------------------------------------------------------
extern "C" void kernel_launch(void* const* d_in, const int* in_sizes, int n_in,
                              void* d_out, int out_size) {
    const float* x = (const float*)d_in[0];
    const int*   y = (const int*)d_in[1];
    float* out = (float*)d_out;

    cudaFuncSetAttribute(snn_main, cudaFuncAttributeMaxDynamicSharedMemorySize, SMEM_SZ);

    snn_prep<<<B / 8, 256>>>(x, y);
    snn_main<<<NTILES, NT, SMEM_SZ>>>();
    snn_fin1<<<16, 256>>>();
    snn_fin2<<<1, 32>>>(out);
}

// round 7
// speedup vs baseline: 7.0264x; 1.9778x over previous
#include <cuda_runtime.h>
#include <cuda_bf16.h>
#include <cstdint>

#define B 4096
#define D 128
#define TEMP 100.0f
#define NT 512
#define NBLK 16                        // 256-row blocks
#define NTILES (NBLK * (NBLK + 1) / 2) // 136
#define BS (B * 64)                    // elems per plane (B rows x 128B)

// smem map
#define SM_A     0                     // Ah0,Ah1 : 2 x 32768
#define SM_B     65536                 // 2 bufs x (Bh0,Bh1 : 2 x 8192)
#define SM_META  98304                 // sqr[256] sqc[256] labr[256] labc[256]
#define SM_RED   102400                // rowD[512] rowN[512] colD[512] colN[512]
#define SM_MB    110592                // mbarA, mbarB0, mbarB1
#define SMEM_SZ  110720

// gmem: 2 planes (h0,h1), each row 128B, SW128 pre-swizzled per 1024B block
__device__ __align__(1024) __nv_bfloat16 g_xs[2 * BS];
__device__ __align__(16) float g_sq[B];
__device__ int   g_lab[B];
__device__ float g_pd[NBLK][B];
__device__ float g_pn[NBLK][B];
__device__ float g_part[16];
__device__ unsigned int g_cnt;

__device__ __forceinline__ uint32_t smem_to_u32(const void* p) {
    uint32_t a;
    asm("{ .reg .u64 t; cvta.to.shared.u64 t, %1; cvt.u32.u64 %0, t; }"
        : "=r"(a) : "l"(p));
    return a;
}
__device__ __forceinline__ uint32_t swz(uint32_t x) { return x ^ ((x >> 3) & 0x70); }

#define MBAR_INIT(m, c) \
    asm volatile("mbarrier.init.shared.b64 [%0], %1;" \
                 :: "r"((uint32_t)(m)), "r"((uint32_t)(c)) : "memory")
#define MBAR_EXPECT(m, n) \
    asm volatile("mbarrier.arrive.expect_tx.shared.b64 _, [%0], %1;" \
                 :: "r"((uint32_t)(m)), "r"((uint32_t)(n)) : "memory")
#define MBAR_WAIT(m, par) do { \
    uint32_t _m = (uint32_t)(m); uint32_t _p = (uint32_t)(par); uint32_t _d; \
    asm volatile("{\n\t.reg .pred p;\n\t" \
        "mbarrier.try_wait.parity.acquire.cta.shared::cta.b64 p, [%1], %2;\n\t" \
        "selp.b32 %0, 1, 0, p;\n\t}" : "=r"(_d) : "r"(_m), "r"(_p) : "memory"); \
    if (!_d) { \
        asm volatile("{\n\t.reg .pred P1;\n\t" \
            "WL_%=:\n\t" \
            "mbarrier.try_wait.parity.acquire.cta.shared::cta.b64 P1, [%0], %1, 0x989680;\n\t" \
            "@P1 bra.uni WD_%=;\n\tbra.uni WL_%=;\n\tWD_%=:\n\t}" \
            :: "r"(_m), "r"(_p) : "memory"); \
    } } while (0)

__device__ __forceinline__ void bulk_cp(uint32_t dst, const void* src,
                                        uint32_t bytes, uint32_t mbar) {
    asm volatile(
        "cp.async.bulk.shared::cluster.global.mbarrier::complete_tx::bytes "
        "[%0], [%1], %2, [%3];"
        :: "r"(dst), "l"(src), "r"(bytes), "r"(mbar) : "memory");
}

#define LDSM_X4(r0, r1, r2, r3, addr) \
    asm volatile("ldmatrix.sync.aligned.m8n8.x4.shared.b16 {%0,%1,%2,%3}, [%4];" \
                 : "=r"(r0), "=r"(r1), "=r"(r2), "=r"(r3) : "r"(addr))
#define MMA16816(c, a, b0, b1) \
    asm volatile("mma.sync.aligned.m16n8k16.row.col.f32.bf16.bf16.f32 " \
                 "{%0,%1,%2,%3}, {%4,%5,%6,%7}, {%8,%9}, {%0,%1,%2,%3};" \
                 : "+f"((c)[0]), "+f"((c)[1]), "+f"((c)[2]), "+f"((c)[3]) \
                 : "r"((a)[0]), "r"((a)[1]), "r"((a)[2]), "r"((a)[3]), \
                   "r"(b0), "r"(b1))

// ---------------------------------------------------------------------------
// Prep: per-row norm + label + bf16 hi split into pre-swizzled planes.
// One warp per row. Block 0 thread 0 also resets the finalize counter.
// ---------------------------------------------------------------------------
__global__ void snn_prep(const float* __restrict__ x, const int* __restrict__ y) {
    if (blockIdx.x == 0 && threadIdx.x == 0) g_cnt = 0;
    int gw = (blockIdx.x * blockDim.x + threadIdx.x) >> 5;
    int lane = threadIdx.x & 31;
    if (gw >= B) return;
    float4 v = reinterpret_cast<const float4*>(x + (size_t)gw * D)[lane];
    float s = v.x * v.x + v.y * v.y + v.z * v.z + v.w * v.w;
    #pragma unroll
    for (int o = 16; o; o >>= 1) s += __shfl_xor_sync(0xFFFFFFFFu, s, o);
    float vv[4] = {v.x, v.y, v.z, v.w};
    __nv_bfloat16 h[4];
    #pragma unroll
    for (int i = 0; i < 4; i++) h[i] = __float2bfloat16(vv[i]);
    int k = lane * 4;
    int hseg = k >> 6;
    uint32_t sby = swz((uint32_t)gw * 128 + (k & 63) * 2);
    char* base = reinterpret_cast<char*>(g_xs);
    *reinterpret_cast<uint2*>(base + (size_t)hseg * (BS * 2) + sby) =
        *reinterpret_cast<uint2*>(h);
    if (lane == 0) { g_sq[gw] = s; g_lab[gw] = y[gw]; }
}

// ---------------------------------------------------------------------------
// One K=128 MMA pass over a 32x32 warp tile. Plane 1 at +32768 (A) / +bstride (B).
// ---------------------------------------------------------------------------
__device__ __forceinline__ void mma_pass(float acc[2][4][4],
                                         uint32_t abase, uint32_t bbase,
                                         uint32_t bstride,
                                         uint32_t pa, uint32_t pb) {
    #pragma unroll
    for (int ks = 0; ks < 8; ks++) {
        const uint32_t koff = (ks & 3) * 32;
        const uint32_t ka = abase + (ks >> 2) * 32768;
        const uint32_t kb = bbase + (ks >> 2) * bstride;
        uint32_t a0[4], a1[4], b0[4], b1[4];
        LDSM_X4(a0[0], a0[1], a0[2], a0[3], ka + swz(pa + koff));
        LDSM_X4(a1[0], a1[1], a1[2], a1[3], ka + swz(pa + 2048 + koff));
        LDSM_X4(b0[0], b0[1], b0[2], b0[3], kb + swz(pb + koff));
        LDSM_X4(b1[0], b1[1], b1[2], b1[3], kb + swz(pb + 2048 + koff));
        MMA16816(acc[0][0], a0, b0[0], b0[1]);
        MMA16816(acc[0][1], a0, b0[2], b0[3]);
        MMA16816(acc[0][2], a0, b1[0], b1[1]);
        MMA16816(acc[0][3], a0, b1[2], b1[3]);
        MMA16816(acc[1][0], a1, b0[0], b0[1]);
        MMA16816(acc[1][1], a1, b0[2], b0[3]);
        MMA16816(acc[1][2], a1, b1[0], b1[1]);
        MMA16816(acc[1][3], a1, b1[2], b1[3]);
    }
}

// ---------------------------------------------------------------------------
// Main: one 256x256 Gram tile per CTA, triangle of 16 blocks (136 CTAs).
// A resident; B streamed in 64-row chunks, double-buffered bulk-async.
// 16 warps 8x2, warp tile 32x32. Single-pass bf16 Gram.
// ---------------------------------------------------------------------------
__global__ void __launch_bounds__(NT, 1)
snn_main() {
    extern __shared__ char smem[];
    uint32_t sb = smem_to_u32(smem);
    const int tid = threadIdx.x;
    const int lane = tid & 31;
    const int w = tid >> 5, wr = w >> 1, wc = w & 1;
    const int grp = lane >> 3, l7 = lane & 7;
    const float NEGC = -1.4426950408889634f / TEMP;

    int t = blockIdx.x, bi = 0;
    while (t >= NBLK - bi) { t -= NBLK - bi; bi++; }
    const int bj = bi + t;
    const bool diag = (bi == bj);
    const int row0 = bi * 256, col0 = bj * 256;

    const uint32_t mbA  = sb + SM_MB;
    const uint32_t mbB0 = sb + SM_MB + 8;
    const uint32_t mbB1 = sb + SM_MB + 16;

    if (tid == 0) { MBAR_INIT(mbA, 1); MBAR_INIT(mbB0, 1); MBAR_INIT(mbB1, 1); }
    __syncthreads();

    const char* gx = reinterpret_cast<const char*>(g_xs);
    if (tid == 0) {
        MBAR_EXPECT(mbA, 65536);
        #pragma unroll
        for (int s = 0; s < 2; s++)
            bulk_cp(sb + SM_A + s * 32768,
                    gx + (size_t)s * (BS * 2) + (size_t)row0 * 128, 32768, mbA);
        if (!diag) {
            MBAR_EXPECT(mbB0, 16384);
            #pragma unroll
            for (int s = 0; s < 2; s++)
                bulk_cp(sb + SM_B + s * 8192,
                        gx + (size_t)s * (BS * 2) + (size_t)col0 * 128, 8192, mbB0);
        }
    }

    float* sqr  = reinterpret_cast<float*>(smem + SM_META);
    float* sqc  = sqr + 256;
    int*   labr = reinterpret_cast<int*>(sqc + 256);
    int*   labc = labr + 256;
    {
        int i = tid;
        if (i < 256) { sqr[i] = g_sq[row0 + i];  labr[i] = g_lab[row0 + i]; }
        else         { sqc[i - 256] = g_sq[col0 + i - 256];
                       labc[i - 256] = g_lab[col0 + i - 256]; }
    }
    __syncthreads();

    const uint32_t pa = (uint32_t)((wr * 32 + (grp & 1) * 8 + l7) * 128 + (grp >> 1) * 16);
    const uint32_t pb = (uint32_t)((wc * 32 + (grp >> 1) * 8 + l7) * 128 + (grp & 1) * 16);
    const int rbase = lane >> 2, cpair = (lane & 3) * 2;

    float sqi[4]; int labi[4];
    #pragma unroll
    for (int i = 0; i < 4; i++) {
        int rloc = wr * 32 + (i >> 1) * 16 + (i & 1) * 8 + rbase;
        sqi[i] = sqr[rloc];  labi[i] = labr[rloc];
    }
    float rs_d[4] = {0.f, 0.f, 0.f, 0.f}, rs_n[4] = {0.f, 0.f, 0.f, 0.f};

    float* rowD = reinterpret_cast<float*>(smem + SM_RED);
    float* rowN = rowD + 512;
    float* colD = rowN + 512;
    float* colN = colD + 512;

    MBAR_WAIT(mbA, 0);

    for (int c = 0; c < 4; c++) {
        if (!diag) {
            if (tid == 0 && c < 3) {
                uint32_t mb = (c & 1) ? mbB0 : mbB1;
                MBAR_EXPECT(mb, 16384);
                #pragma unroll
                for (int s = 0; s < 2; s++)
                    bulk_cp(sb + SM_B + (uint32_t)(((c + 1) & 1) * 16384 + s * 8192),
                            gx + (size_t)s * (BS * 2)
                               + (size_t)(col0 + (c + 1) * 64) * 128, 8192, mb);
            }
            MBAR_WAIT((c & 1) ? mbB1 : mbB0, (c >> 1) & 1);
        }

        float acc[2][4][4];
        #pragma unroll
        for (int mt = 0; mt < 2; mt++)
            #pragma unroll
            for (int nt = 0; nt < 4; nt++)
                #pragma unroll
                for (int e = 0; e < 4; e++) acc[mt][nt][e] = 0.f;

        uint32_t aH = sb + SM_A;
        uint32_t bH, bstr;
        if (diag) { bH = aH + c * 8192;  bstr = 32768; }
        else      { bH = sb + SM_B + (uint32_t)((c & 1) * 16384);  bstr = 8192; }
        mma_pass(acc, aH, bH, bstr, pa, pb);

        // ---- epilogue for this 256x64 chunk ----
        float sqjt[8]; int labjt[8];
        #pragma unroll
        for (int k = 0; k < 8; k++) {
            int cloc = wc * 32 + (k >> 1) * 8 + cpair + (k & 1);
            sqjt[k] = sqc[c * 64 + cloc];  labjt[k] = labc[c * 64 + cloc];
        }
        float cs_d[8] = {0,0,0,0,0,0,0,0}, cs_n[8] = {0,0,0,0,0,0,0,0};

        #pragma unroll
        for (int mt = 0; mt < 2; mt++)
            #pragma unroll
            for (int nt = 0; nt < 4; nt++)
                #pragma unroll
                for (int e = 0; e < 4; e++) {
                    int half = e >> 1, p = e & 1;
                    int i = mt * 2 + half, k = nt * 2 + p;
                    int gi  = row0 + wr * 32 + mt * 16 + half * 8 + rbase;
                    int col = col0 + c * 64 + wc * 32 + nt * 8 + cpair + p;
                    float dist = sqi[i] + sqjt[k] - 2.f * acc[mt][nt][e];
                    dist = fmaxf(dist, 0.f);
                    float ev = exp2f(dist * NEGC);
                    bool self = (gi == col);
                    if (self) ev = 1.f;
                    float nv = (labi[i] == labjt[k] && !self) ? ev : 0.f;
                    rs_d[i] += ev;  rs_n[i] += nv;
                    cs_d[k] += ev;  cs_n[k] += nv;
                }

        if (!diag) {
            #pragma unroll
            for (int k = 0; k < 8; k++) {
                cs_d[k] += __shfl_xor_sync(0xFFFFFFFFu, cs_d[k], 4);
                cs_d[k] += __shfl_xor_sync(0xFFFFFFFFu, cs_d[k], 8);
                cs_d[k] += __shfl_xor_sync(0xFFFFFFFFu, cs_d[k], 16);
                cs_n[k] += __shfl_xor_sync(0xFFFFFFFFu, cs_n[k], 4);
                cs_n[k] += __shfl_xor_sync(0xFFFFFFFFu, cs_n[k], 8);
                cs_n[k] += __shfl_xor_sync(0xFFFFFFFFu, cs_n[k], 16);
            }
            __syncthreads();
            if (lane < 4) {
                #pragma unroll
                for (int k = 0; k < 8; k++) {
                    int cloc = wc * 32 + (k >> 1) * 8 + lane * 2 + (k & 1);
                    colD[wr * 64 + cloc] = cs_d[k];
                    colN[wr * 64 + cloc] = cs_n[k];
                }
            }
            __syncthreads();
            if (tid < 64) {
                float sd = 0.f, sn = 0.f;
                #pragma unroll
                for (int s = 0; s < 8; s++) { sd += colD[s * 64 + tid]; sn += colN[s * 64 + tid]; }
                g_pd[bi][col0 + c * 64 + tid] = sd;
                g_pn[bi][col0 + c * 64 + tid] = sn;
            }
        }
        __syncthreads();
    }

    // ---- row-sum cross-warp reduce + store ----
    #pragma unroll
    for (int i = 0; i < 4; i++) {
        rs_d[i] += __shfl_xor_sync(0xFFFFFFFFu, rs_d[i], 1);
        rs_d[i] += __shfl_xor_sync(0xFFFFFFFFu, rs_d[i], 2);
        rs_n[i] += __shfl_xor_sync(0xFFFFFFFFu, rs_n[i], 1);
        rs_n[i] += __shfl_xor_sync(0xFFFFFFFFu, rs_n[i], 2);
    }
    if ((lane & 3) == 0) {
        #pragma unroll
        for (int i = 0; i < 4; i++) {
            int rloc = wr * 32 + (i >> 1) * 16 + (i & 1) * 8 + rbase;
            rowD[wc * 256 + rloc] = rs_d[i];
            rowN[wc * 256 + rloc] = rs_n[i];
        }
    }
    __syncthreads();
    if (tid < 256) {
        g_pd[bj][row0 + tid] = rowD[tid] + rowD[256 + tid];
        g_pn[bj][row0 + tid] = rowN[tid] + rowN[256 + tid];
    }
}

// ---------------------------------------------------------------------------
// Finalize (fused): per-row loss partials; last block sums and writes out.
// ---------------------------------------------------------------------------
__global__ void snn_fin(float* __restrict__ out) {
    __shared__ float sred[256];
    int i = blockIdx.x * 256 + threadIdx.x;
    float den = 0.f, num = 0.f;
    #pragma unroll
    for (int p = 0; p < NBLK; p++) { den += g_pd[p][i]; num += g_pn[p][i]; }
    float s = logf(den) - logf(num);
    sred[threadIdx.x] = s;
    __syncthreads();
    for (int off = 128; off > 0; off >>= 1) {
        if (threadIdx.x < off) sred[threadIdx.x] += sred[threadIdx.x + off];
        __syncthreads();
    }
    if (threadIdx.x == 0) {
        g_part[blockIdx.x] = sred[0];
        __threadfence();
        unsigned int old = atomicAdd(&g_cnt, 1u);
        if (old == 15u) {
            float tot = 0.f;
            #pragma unroll
            for (int b = 0; b < 16; b++) tot += g_part[b];
            out[0] = tot / (float)B;
        }
    }
}

// ---------------------------------------------------------------------------
extern "C" void kernel_launch(void* const* d_in, const int* in_sizes, int n_in,
                              void* d_out, int out_size) {
    const float* x = (const float*)d_in[0];
    const int*   y = (const int*)d_in[1];
    float* out = (float*)d_out;

    cudaFuncSetAttribute(snn_main, cudaFuncAttributeMaxDynamicSharedMemorySize, SMEM_SZ);

    snn_prep<<<B / 8, 256>>>(x, y);
    snn_main<<<NTILES, NT, SMEM_SZ>>>();
    snn_fin<<<16, 256>>>(out);
}